// round 9
// baseline (speedup 1.0000x reference)
#include <cuda_runtime.h>

#define N_NODES 320000
#define F_IN    128
#define L       10
#define CAP     80
#define N_EDGES 10240000
#define EHALF   (N_EDGES / 2)
#define FULL    0xffffffffu

static __device__ int    g_cnt[N_NODES];
static __device__ float  g_dis[N_NODES];
static __device__ float4 g_hwA[(size_t)N_NODES * 4];   // 16-float padded rows (64B)
static __device__ float4 g_hwB[(size_t)N_NODES * 4];
static __device__ float4 g_agg[(size_t)N_NODES * 4];   // gather results
static __device__ int    g_csr[(size_t)N_NODES * CAP];

// ---------------------------------------------------------------------------
// 1) Bucket scatter, 2 independent edge chains/thread (ILP over ATOMG latency)
// ---------------------------------------------------------------------------
__global__ void k_scatter(const int* __restrict__ ei) {
    int e = blockIdx.x * blockDim.x + threadIdx.x;
    if (e >= EHALF) return;
    const int* rp = ei;
    const int* cp = ei + N_EDGES;
    int r0 = __ldg(&rp[e]);
    int c0 = __ldg(&cp[e]);
    int r1 = __ldg(&rp[e + EHALF]);
    int c1 = __ldg(&cp[e + EHALF]);
    int p0 = atomicAdd(&g_cnt[c0], 1);
    int p1 = atomicAdd(&g_cnt[c1], 1);
    if (p0 < CAP) g_csr[(size_t)c0 * CAP + p0] = r0;
    if (p1 < CAP) g_csr[(size_t)c1 * CAP + p1] = r1;
}

// ---------------------------------------------------------------------------
// 2) Input (graph-independent, overlapped with scatter):
//    hwA[n] = relu(x@Win + bin) @ W1   (UNSCALED)
// ---------------------------------------------------------------------------
__global__ void k_input(const float* __restrict__ x, const float* __restrict__ Win,
                        const float* __restrict__ bin, const float* __restrict__ W1) {
    __shared__ float sW[F_IN * L];
    __shared__ float sB[L];
    __shared__ float sW1[L * L];
    for (int i = threadIdx.x; i < F_IN * L; i += blockDim.x) sW[i] = Win[i];
    for (int i = threadIdx.x; i < L * L;   i += blockDim.x) sW1[i] = W1[i];
    if (threadIdx.x < L) sB[threadIdx.x] = bin[threadIdx.x];
    __syncthreads();

    int t  = blockIdx.x * blockDim.x + threadIdx.x;
    int n0 = 2 * t;
    if (n0 >= N_NODES) return;
    int n1 = n0 + 1;

    float acc0[L], acc1[L];
    #pragma unroll
    for (int j = 0; j < L; j++) { acc0[j] = 0.f; acc1[j] = 0.f; }

    const float4* x0 = (const float4*)(x + (size_t)n0 * F_IN);
    const float4* x1 = (const float4*)(x + (size_t)n1 * F_IN);

    #pragma unroll 4
    for (int kq = 0; kq < F_IN / 4; kq++) {
        float4 a = x0[kq];
        float4 b = x1[kq];
        float va[4] = {a.x, a.y, a.z, a.w};
        float vb[4] = {b.x, b.y, b.z, b.w};
        #pragma unroll
        for (int u = 0; u < 4; u++) {
            int k = kq * 4 + u;
            #pragma unroll
            for (int j = 0; j < L; j++) {
                float w = sW[k * L + j];
                acc0[j] = fmaf(va[u], w, acc0[j]);
                acc1[j] = fmaf(vb[u], w, acc1[j]);
            }
        }
    }

    float h0[L], h1[L];
    #pragma unroll
    for (int j = 0; j < L; j++) {
        h0[j] = fmaxf(acc0[j] + sB[j], 0.f);
        h1[j] = fmaxf(acc1[j] + sB[j], 0.f);
    }

    float t0[L], t1[L];
    #pragma unroll
    for (int j = 0; j < L; j++) { t0[j] = 0.f; t1[j] = 0.f; }
    #pragma unroll
    for (int l = 0; l < L; l++) {
        #pragma unroll
        for (int j = 0; j < L; j++) {
            float w = sW1[l * L + j];
            t0[j] = fmaf(h0[l], w, t0[j]);
            t1[j] = fmaf(h1[l], w, t1[j]);
        }
    }

    float4* o0 = &g_hwA[(size_t)n0 * 4];
    float4* o1 = &g_hwA[(size_t)n1 * 4];
    o0[0] = make_float4(t0[0], t0[1], t0[2], t0[3]);
    o0[1] = make_float4(t0[4], t0[5], t0[6], t0[7]);
    o0[2] = make_float4(t0[8], t0[9], 0.f, 0.f);
    o0[3] = make_float4(0.f, 0.f, 0.f, 0.f);
    o1[0] = make_float4(t1[0], t1[1], t1[2], t1[3]);
    o1[1] = make_float4(t1[4], t1[5], t1[6], t1[7]);
    o1[2] = make_float4(t1[8], t1[9], 0.f, 0.f);
    o1[3] = make_float4(0.f, 0.f, 0.f, 0.f);
}

// ---------------------------------------------------------------------------
// 2b) Join: dis = rsqrt(deg+2); hwA *= dis
// ---------------------------------------------------------------------------
__global__ void k_scale() {
    int i = blockIdx.x * blockDim.x + threadIdx.x;      // float4 index
    if (i >= N_NODES * 4) return;
    int n = i >> 2;
    float dis = rsqrtf((float)g_cnt[n] + 2.0f);
    if ((i & 3) == 0) g_dis[n] = dis;
    float4 v = g_hwA[i];
    v.x *= dis; v.y *= dis; v.z *= dis; v.w *= dis;
    g_hwA[i] = v;
}

// ---------------------------------------------------------------------------
// 3) Pure gather, software-pipelined index prefetch:
//    agg[n] = Σ_{r in bucket(n)} src[r]   (warp/node, 4 lanes/edge)
// ---------------------------------------------------------------------------
__global__ void k_gath(const float4* __restrict__ src) {
    int n = (blockIdx.x * blockDim.x + threadIdx.x) >> 5;
    if (n >= N_NODES) return;
    int lane = threadIdx.x & 31;
    int sub  = lane >> 2;
    int c    = lane & 3;

    int cnt = g_cnt[n];
    if (cnt > CAP) cnt = CAP;
    const int* bucket = &g_csr[(size_t)n * CAP];

    float4 acc = make_float4(0.f, 0.f, 0.f, 0.f);
    int i = sub;
    int r = (i < cnt) ? __ldg(&bucket[i]) : 0;
    while (i < cnt) {
        int inext = i + 8;
        int rn = (inext < cnt) ? __ldg(&bucket[inext]) : 0;  // prefetch next idx
        float4 v = __ldg(&src[(size_t)r * 4 + c]);
        acc.x += v.x; acc.y += v.y; acc.z += v.z; acc.w += v.w;
        r = rn;
        i = inext;
    }
    #pragma unroll
    for (int s = 4; s < 32; s <<= 1) {
        acc.x += __shfl_xor_sync(FULL, acc.x, s);
        acc.y += __shfl_xor_sync(FULL, acc.y, s);
        acc.z += __shfl_xor_sync(FULL, acc.z, s);
        acc.w += __shfl_xor_sync(FULL, acc.w, s);
    }
    if (lane < 4) g_agg[(size_t)n * 4 + c] = acc;       // 64B coalesced
}

// ---------------------------------------------------------------------------
// 4) Finalize layer 1 (thread/node, coalesced):
//    h = relu(dis*(agg + 2*hwA) + b1);  hwB = dis * (h @ W2)
// ---------------------------------------------------------------------------
__global__ void k_fin1(const float* __restrict__ b1, const float* __restrict__ W2) {
    __shared__ float sW[L * L];
    __shared__ float sB[L];
    for (int i = threadIdx.x; i < L * L; i += blockDim.x) sW[i] = W2[i];
    if (threadIdx.x < L) sB[threadIdx.x] = b1[threadIdx.x];
    __syncthreads();

    int n = blockIdx.x * blockDim.x + threadIdx.x;
    if (n >= N_NODES) return;

    float dis = g_dis[n];
    const float4* ag = &g_agg[(size_t)n * 4];
    const float4* hw = &g_hwA[(size_t)n * 4];
    float4 a0 = ag[0], a1 = ag[1], a2 = ag[2];
    float4 s0 = hw[0], s1 = hw[1], s2 = hw[2];

    float h[L];
    h[0] = fmaxf(dis * (a0.x + 2.f * s0.x) + sB[0], 0.f);
    h[1] = fmaxf(dis * (a0.y + 2.f * s0.y) + sB[1], 0.f);
    h[2] = fmaxf(dis * (a0.z + 2.f * s0.z) + sB[2], 0.f);
    h[3] = fmaxf(dis * (a0.w + 2.f * s0.w) + sB[3], 0.f);
    h[4] = fmaxf(dis * (a1.x + 2.f * s1.x) + sB[4], 0.f);
    h[5] = fmaxf(dis * (a1.y + 2.f * s1.y) + sB[5], 0.f);
    h[6] = fmaxf(dis * (a1.z + 2.f * s1.z) + sB[6], 0.f);
    h[7] = fmaxf(dis * (a1.w + 2.f * s1.w) + sB[7], 0.f);
    h[8] = fmaxf(dis * (a2.x + 2.f * s2.x) + sB[8], 0.f);
    h[9] = fmaxf(dis * (a2.y + 2.f * s2.y) + sB[9], 0.f);

    float t[L];
    #pragma unroll
    for (int j = 0; j < L; j++) t[j] = 0.f;
    #pragma unroll
    for (int l = 0; l < L; l++) {
        #pragma unroll
        for (int j = 0; j < L; j++)
            t[j] = fmaf(h[l], sW[l * L + j], t[j]);
    }

    float4* o = &g_hwB[(size_t)n * 4];
    o[0] = make_float4(dis*t[0], dis*t[1], dis*t[2], dis*t[3]);
    o[1] = make_float4(dis*t[4], dis*t[5], dis*t[6], dis*t[7]);
    o[2] = make_float4(dis*t[8], dis*t[9], 0.f, 0.f);
    o[3] = make_float4(0.f, 0.f, 0.f, 0.f);
}

// ---------------------------------------------------------------------------
// 5) Finalize layer 2 + output:
//    out = relu(dis*(agg + 2*hwB) + b2) @ Wout + bout
// ---------------------------------------------------------------------------
__global__ void k_fin2(const float* __restrict__ b2, const float* __restrict__ Wout,
                       const float* __restrict__ bout, float* __restrict__ out) {
    __shared__ float sWo[L];
    __shared__ float sB[L];
    __shared__ float sb0;
    if (threadIdx.x < L) { sWo[threadIdx.x] = Wout[threadIdx.x]; sB[threadIdx.x] = b2[threadIdx.x]; }
    if (threadIdx.x == 0) sb0 = bout[0];
    __syncthreads();

    int n = blockIdx.x * blockDim.x + threadIdx.x;
    if (n >= N_NODES) return;

    float dis = g_dis[n];
    const float4* ag = &g_agg[(size_t)n * 4];
    const float4* hw = &g_hwB[(size_t)n * 4];
    float4 a0 = ag[0], a1 = ag[1], a2 = ag[2];
    float4 s0 = hw[0], s1 = hw[1], s2 = hw[2];

    float acc = sb0;
    acc = fmaf(fmaxf(dis * (a0.x + 2.f * s0.x) + sB[0], 0.f), sWo[0], acc);
    acc = fmaf(fmaxf(dis * (a0.y + 2.f * s0.y) + sB[1], 0.f), sWo[1], acc);
    acc = fmaf(fmaxf(dis * (a0.z + 2.f * s0.z) + sB[2], 0.f), sWo[2], acc);
    acc = fmaf(fmaxf(dis * (a0.w + 2.f * s0.w) + sB[3], 0.f), sWo[3], acc);
    acc = fmaf(fmaxf(dis * (a1.x + 2.f * s1.x) + sB[4], 0.f), sWo[4], acc);
    acc = fmaf(fmaxf(dis * (a1.y + 2.f * s1.y) + sB[5], 0.f), sWo[5], acc);
    acc = fmaf(fmaxf(dis * (a1.z + 2.f * s1.z) + sB[6], 0.f), sWo[6], acc);
    acc = fmaf(fmaxf(dis * (a1.w + 2.f * s1.w) + sB[7], 0.f), sWo[7], acc);
    acc = fmaf(fmaxf(dis * (a2.x + 2.f * s2.x) + sB[8], 0.f), sWo[8], acc);
    acc = fmaf(fmaxf(dis * (a2.y + 2.f * s2.y) + sB[9], 0.f), sWo[9], acc);
    out[n] = acc;
}

extern "C" void kernel_launch(void* const* d_in, const int* in_sizes, int n_in,
                              void* d_out, int out_size) {
    const float* x    = (const float*)d_in[0];
    const int*   ei   = (const int*)  d_in[1];
    const float* Win  = (const float*)d_in[2];
    const float* bin  = (const float*)d_in[3];
    const float* W1   = (const float*)d_in[4];
    const float* b1   = (const float*)d_in[5];
    const float* W2   = (const float*)d_in[6];
    const float* b2   = (const float*)d_in[7];
    const float* Wout = (const float*)d_in[8];
    const float* bout = (const float*)d_in[9];
    float* out = (float*)d_out;

    void *cnt_p = nullptr, *hwA_p = nullptr, *hwB_p = nullptr;
    cudaGetSymbolAddress(&cnt_p, g_cnt);
    cudaGetSymbolAddress(&hwA_p, g_hwA);
    cudaGetSymbolAddress(&hwB_p, g_hwB);

    static cudaStream_t s1 = nullptr;
    static cudaEvent_t evFork = nullptr, evJoin = nullptr;
    if (s1 == nullptr) {
        cudaStreamCreateWithFlags(&s1, cudaStreamNonBlocking);
        cudaEventCreateWithFlags(&evFork, cudaEventDisableTiming);
        cudaEventCreateWithFlags(&evJoin, cudaEventDisableTiming);
    }

    const int TB = 256;
    int eb = (EHALF + TB - 1) / TB;
    int ib = (N_NODES / 2 + TB - 1) / TB;
    int sc = (N_NODES * 4 + TB - 1) / TB;
    int nb = (N_NODES + TB - 1) / TB;
    int gb = N_NODES / 8;

    // Fork: side stream runs the graph-independent input GEMV chain
    cudaEventRecord(evFork, 0);
    cudaStreamWaitEvent(s1, evFork, 0);
    k_input<<<ib, TB, 0, s1>>>(x, Win, bin, W1);
    cudaEventRecord(evJoin, s1);

    // Main stream: build buckets (concurrent with k_input)
    cudaMemsetAsync(cnt_p, 0, (size_t)N_NODES * sizeof(int));
    k_scatter<<<eb, TB>>>(ei);

    // Join, then scale + gather/finalize pairs
    cudaStreamWaitEvent(0, evJoin, 0);
    k_scale<<<sc, TB>>>();
    k_gath<<<gb, TB>>>((const float4*)hwA_p);
    k_fin1<<<nb, TB>>>(b1, W2);
    k_gath<<<gb, TB>>>((const float4*)hwB_p);
    k_fin2<<<nb, TB>>>(b2, Wout, bout, out);
}